// round 2
// baseline (speedup 1.0000x reference)
#include <cuda_runtime.h>

#define NNODES 100000
#define EEDGES 1600000
#define HID    128
#define NCLS   40

typedef unsigned long long ull;

// ---------------- scratch (device globals; no allocation allowed) ------------
__device__ __align__(128) float g_h1[NNODES * HID];
__device__ __align__(128) float g_h2[NNODES * HID];
__device__ __align__(128) float g_agg[NNODES * HID];
__device__ int   g_outdeg[NNODES];
__device__ int   g_indeg[NNODES];
__device__ int   g_cursor[NNODES];
__device__ float g_onorm[NNODES];
__device__ float g_inorm[NNODES];
__device__ int   g_rowoff[NNODES + 1];
__device__ int   g_bsums[256];
__device__ int   g_esrc[EEDGES];

// ---------------- small prep kernels ----------------------------------------
__global__ void zero_ints_kernel(int n) {
    int i = blockIdx.x * blockDim.x + threadIdx.x;
    if (i < n) { g_outdeg[i] = 0; g_indeg[i] = 0; g_cursor[i] = 0; }
}

__global__ void degree_kernel(const int* __restrict__ src,
                              const int* __restrict__ dst, int E) {
    int e = blockIdx.x * blockDim.x + threadIdx.x;
    if (e < E) {
        atomicAdd(&g_outdeg[src[e]], 1);
        atomicAdd(&g_indeg[dst[e]], 1);
    }
}

__global__ void norm_kernel(int n) {
    int i = blockIdx.x * blockDim.x + threadIdx.x;
    if (i < n) {
        g_onorm[i] = rsqrtf((float)max(g_outdeg[i], 1));
        g_inorm[i] = rsqrtf((float)max(g_indeg[i], 1));
    }
}

// exclusive scan of g_indeg -> g_rowoff (3 phases)
__global__ void scan1_kernel(int n) {
    __shared__ int s[1024];
    int tid = threadIdx.x;
    int i = blockIdx.x * 1024 + tid;
    int v = (i < n) ? g_indeg[i] : 0;
    s[tid] = v;
    __syncthreads();
    #pragma unroll
    for (int off = 1; off < 1024; off <<= 1) {
        int t = 0;
        if (tid >= off) t = s[tid - off];
        __syncthreads();
        s[tid] += t;
        __syncthreads();
    }
    if (i < n) g_rowoff[i] = s[tid] - v;   // exclusive (block-local)
    if (tid == 1023) g_bsums[blockIdx.x] = s[1023];
}

__global__ void scan2_kernel(int nb, int n, int E) {
    if (threadIdx.x == 0 && blockIdx.x == 0) {
        int run = 0;
        for (int b = 0; b < nb; b++) { int t = g_bsums[b]; g_bsums[b] = run; run += t; }
        g_rowoff[n] = E;
    }
}

__global__ void scan3_kernel(int n) {
    int i = blockIdx.x * 1024 + threadIdx.x;
    if (i < n) g_rowoff[i] += g_bsums[blockIdx.x];
}

__global__ void fill_kernel(const int* __restrict__ src,
                            const int* __restrict__ dst, int E) {
    int e = blockIdx.x * blockDim.x + threadIdx.x;
    if (e < E) {
        int d = dst[e];
        int pos = g_rowoff[d] + atomicAdd(&g_cursor[d], 1);
        g_esrc[pos] = src[e];
    }
}

// ---------------- gather: warp per dst node, pull-mode, no atomics -----------
// aggout[n] = in_norm[n] * sum_{e in CSR[n]} h[src_e] * out_norm[src_e]
__global__ void __launch_bounds__(256)
gather_kernel(const float* __restrict__ h, float* __restrict__ aggout, int n) {
    int gw = (blockIdx.x * blockDim.x + threadIdx.x) >> 5;
    int lane = threadIdx.x & 31;
    if (gw >= n) return;
    int e0 = g_rowoff[gw];
    int e1 = g_rowoff[gw + 1];
    const float4* __restrict__ h4 = (const float4*)h;
    float4 acc = make_float4(0.f, 0.f, 0.f, 0.f);
    int e = e0;
    for (; e + 3 < e1; e += 4) {
        int s0 = g_esrc[e];
        int s1 = g_esrc[e + 1];
        int s2 = g_esrc[e + 2];
        int s3 = g_esrc[e + 3];
        float w0 = g_onorm[s0];
        float w1 = g_onorm[s1];
        float w2 = g_onorm[s2];
        float w3 = g_onorm[s3];
        float4 v0 = h4[s0 * 32 + lane];
        float4 v1 = h4[s1 * 32 + lane];
        float4 v2 = h4[s2 * 32 + lane];
        float4 v3 = h4[s3 * 32 + lane];
        acc.x = fmaf(v0.x, w0, acc.x); acc.y = fmaf(v0.y, w0, acc.y);
        acc.z = fmaf(v0.z, w0, acc.z); acc.w = fmaf(v0.w, w0, acc.w);
        acc.x = fmaf(v1.x, w1, acc.x); acc.y = fmaf(v1.y, w1, acc.y);
        acc.z = fmaf(v1.z, w1, acc.z); acc.w = fmaf(v1.w, w1, acc.w);
        acc.x = fmaf(v2.x, w2, acc.x); acc.y = fmaf(v2.y, w2, acc.y);
        acc.z = fmaf(v2.z, w2, acc.z); acc.w = fmaf(v2.w, w2, acc.w);
        acc.x = fmaf(v3.x, w3, acc.x); acc.y = fmaf(v3.y, w3, acc.y);
        acc.z = fmaf(v3.z, w3, acc.z); acc.w = fmaf(v3.w, w3, acc.w);
    }
    for (; e < e1; e++) {
        int s0 = g_esrc[e];
        float w0 = g_onorm[s0];
        float4 v0 = h4[s0 * 32 + lane];
        acc.x = fmaf(v0.x, w0, acc.x); acc.y = fmaf(v0.y, w0, acc.y);
        acc.z = fmaf(v0.z, w0, acc.z); acc.w = fmaf(v0.w, w0, acc.w);
    }
    float inn = g_inorm[gw];
    float4 r = make_float4(acc.x * inn, acc.y * inn, acc.z * inn, acc.w * inn);
    ((float4*)aggout)[gw * 32 + lane] = r;
}

// ---------------- GEMM: C[M,128] = A[M,128] @ W[128,128] + b (opt relu) ------
// block: 256 threads (16x16), tile 128x128, micro 8x8, K-tiles of 16.
// fp32 math via packed fma.rn.f32x2 (FFMA2): accumulators are 8x4 packed
// pairs along columns. W pairs load pre-packed from smem; A broadcast pairs
// come from a DUPLICATED A tile (As2[k][2r]=As2[k][2r+1]=a) so no MOV packing
// appears in the inner loop.
__global__ void __launch_bounds__(256)
gemm128_kernel(const float* __restrict__ A, const float* __restrict__ W,
               const float* __restrict__ bias, float* __restrict__ C,
               int M, int relu) {
    __shared__ float As2[16][256];  // [k][2*row] duplicated pairs
    __shared__ float Ws[16][132];   // [k][col]
    const int tid = threadIdx.x;
    const int tx = tid & 15;
    const int ty = tid >> 4;
    const int rowBase = blockIdx.x << 7;

    ull acc[8][4];
    #pragma unroll
    for (int i = 0; i < 8; i++)
        #pragma unroll
        for (int j = 0; j < 4; j++) acc[i][j] = 0ULL;

    for (int k0 = 0; k0 < 128; k0 += 16) {
        // A tile: 128 rows x 16 k, transposed + duplicated into As2[k][2r(+1)]
        #pragma unroll
        for (int i = 0; i < 2; i++) {
            int idx = tid * 2 + i;          // 0..511
            int r = idx >> 2;               // row 0..127
            int c = idx & 3;                // which float4 of the 16-k strip
            int row = rowBase + r;
            float4 v = make_float4(0.f, 0.f, 0.f, 0.f);
            if (row < M) v = *(const float4*)(A + row * 128 + k0 + c * 4);
            *(float2*)&As2[c * 4 + 0][2 * r] = make_float2(v.x, v.x);
            *(float2*)&As2[c * 4 + 1][2 * r] = make_float2(v.y, v.y);
            *(float2*)&As2[c * 4 + 2][2 * r] = make_float2(v.z, v.z);
            *(float2*)&As2[c * 4 + 3][2 * r] = make_float2(v.w, v.w);
        }
        // W tile: 16 k x 128 cols
        #pragma unroll
        for (int i = 0; i < 2; i++) {
            int idx = tid * 2 + i;          // 0..511
            int kk = idx >> 5;              // 0..15
            int cc = idx & 31;              // float4 index in 128 cols
            float4 w = *(const float4*)(W + (k0 + kk) * 128 + cc * 4);
            *(float4*)(&Ws[kk][cc * 4]) = w;
        }
        __syncthreads();

        #pragma unroll
        for (int k = 0; k < 16; k++) {
            const ulonglong2* pa = (const ulonglong2*)&As2[k][ty * 16];
            ulonglong2 t0 = pa[0], t1 = pa[1], t2 = pa[2], t3 = pa[3];
            ull a2[8] = {t0.x, t0.y, t1.x, t1.y, t2.x, t2.y, t3.x, t3.y};
            const ulonglong2* pw = (const ulonglong2*)&Ws[k][tx * 8];
            ulonglong2 u0 = pw[0], u1 = pw[1];
            ull w2[4] = {u0.x, u0.y, u1.x, u1.y};
            #pragma unroll
            for (int i = 0; i < 8; i++)
                #pragma unroll
                for (int j = 0; j < 4; j++)
                    asm("fma.rn.f32x2 %0, %1, %2, %0;"
                        : "+l"(acc[i][j]) : "l"(a2[i]), "l"(w2[j]));
        }
        __syncthreads();
    }

    float bv[8];
    #pragma unroll
    for (int j = 0; j < 8; j++) bv[j] = bias[tx * 8 + j];

    #pragma unroll
    for (int i = 0; i < 8; i++) {
        int row = rowBase + ty * 8 + i;
        if (row < M) {
            float o[8];
            #pragma unroll
            for (int j = 0; j < 4; j++) {
                float2 p = *(float2*)&acc[i][j];
                float v0 = p.x + bv[2 * j];
                float v1 = p.y + bv[2 * j + 1];
                if (relu) { v0 = fmaxf(v0, 0.f); v1 = fmaxf(v1, 0.f); }
                o[2 * j] = v0; o[2 * j + 1] = v1;
            }
            *(float4*)(C + row * 128 + tx * 8)     = make_float4(o[0], o[1], o[2], o[3]);
            *(float4*)(C + row * 128 + tx * 8 + 4) = make_float4(o[4], o[5], o[6], o[7]);
        }
    }
}

// ---------------- classifier: out[M,40] = A[M,128] @ Wc[128,40] + bc ---------
// warp handles 4 rows; Wc in smem; A row elements broadcast via shfl
__global__ void __launch_bounds__(256)
classifier_kernel(const float* __restrict__ A, const float* __restrict__ Wc,
                  const float* __restrict__ bc, float* __restrict__ out, int M) {
    __shared__ float Ws[128 * 40];
    __shared__ float bs[40];
    for (int i = threadIdx.x; i < 128 * 40; i += 256) Ws[i] = Wc[i];
    if (threadIdx.x < 40) bs[threadIdx.x] = bc[threadIdx.x];
    __syncthreads();

    int lane = threadIdx.x & 31;
    int warp = (blockIdx.x * 256 + threadIdx.x) >> 5;
    int row0 = warp * 4;
    if (row0 >= M) return;

    float4 av[4];
    #pragma unroll
    for (int r = 0; r < 4; r++) {
        int row = row0 + r;
        av[r] = (row < M) ? ((const float4*)A)[row * 32 + lane]
                          : make_float4(0.f, 0.f, 0.f, 0.f);
    }

    float acc0[4] = {0.f, 0.f, 0.f, 0.f};
    float acc1[4] = {0.f, 0.f, 0.f, 0.f};
    bool hi = lane < 8;

    for (int k4 = 0; k4 < 32; k4++) {
        #pragma unroll
        for (int c = 0; c < 4; c++) {
            int k = k4 * 4 + c;
            float w0 = Ws[k * 40 + lane];
            float w1 = hi ? Ws[k * 40 + 32 + lane] : 0.f;
            #pragma unroll
            for (int r = 0; r < 4; r++) {
                float comp = (c == 0) ? av[r].x : (c == 1) ? av[r].y
                           : (c == 2) ? av[r].z : av[r].w;
                float aval = __shfl_sync(0xffffffffu, comp, k4);
                acc0[r] = fmaf(aval, w0, acc0[r]);
                acc1[r] = fmaf(aval, w1, acc1[r]);
            }
        }
    }

    #pragma unroll
    for (int r = 0; r < 4; r++) {
        int row = row0 + r;
        if (row < M) {
            out[row * 40 + lane] = acc0[r] + bs[lane];
            if (hi) out[row * 40 + 32 + lane] = acc1[r] + bs[32 + lane];
        }
    }
}

// ---------------- launch ------------------------------------------------------
extern "C" void kernel_launch(void* const* d_in, const int* in_sizes, int n_in,
                              void* d_out, int out_size) {
    const float* x   = (const float*)d_in[0];
    const int*   src = (const int*)  d_in[1];
    const int*   dst = (const int*)  d_in[2];
    const float* W1  = (const float*)d_in[3];
    const float* b1  = (const float*)d_in[4];
    const float* W2  = (const float*)d_in[5];
    const float* b2  = (const float*)d_in[6];
    const float* Wg  = (const float*)d_in[7];   // [3,128,128]
    const float* bg  = (const float*)d_in[8];   // [3,128]
    const float* Wc  = (const float*)d_in[9];
    const float* bc  = (const float*)d_in[10];
    float* out = (float*)d_out;

    const int N = in_sizes[0] / HID;
    const int E = in_sizes[1];

    float *h1, *h2, *agg;
    cudaGetSymbolAddress((void**)&h1,  g_h1);
    cudaGetSymbolAddress((void**)&h2,  g_h2);
    cudaGetSymbolAddress((void**)&agg, g_agg);

    const int TB = 256;
    const int gN = (N + TB - 1) / TB;
    const int gE = (E + TB - 1) / TB;
    const int nb = (N + 1023) / 1024;
    const int gGemm = (N + 127) / 128;
    const int gGather = (N + 7) / 8;          // 8 warps / block
    const int gCls = (N + 31) / 32;           // 8 warps x 4 rows / block

    // --- graph structure prep (every call; deterministic up to atomic order) ---
    zero_ints_kernel<<<gN, TB>>>(N);
    degree_kernel<<<gE, TB>>>(src, dst, E);
    norm_kernel<<<gN, TB>>>(N);
    scan1_kernel<<<nb, 1024>>>(N);
    scan2_kernel<<<1, 32>>>(nb, N, E);
    scan3_kernel<<<nb, 1024>>>(N);
    fill_kernel<<<gE, TB>>>(src, dst, E);

    // --- MLP front ---
    gemm128_kernel<<<gGemm, TB>>>(x,  W1, b1, h1, N, 0);
    gemm128_kernel<<<gGemm, TB>>>(h1, W2, b2, h2, N, 0);

    // --- 3 x (GraphConv + ReLU) ---
    gather_kernel<<<gGather, TB>>>(h2, agg, N);
    gemm128_kernel<<<gGemm, TB>>>(agg, Wg + 0 * 128 * 128, bg + 0 * 128, h1, N, 1);

    gather_kernel<<<gGather, TB>>>(h1, agg, N);
    gemm128_kernel<<<gGemm, TB>>>(agg, Wg + 1 * 128 * 128, bg + 1 * 128, h2, N, 1);

    gather_kernel<<<gGather, TB>>>(h2, agg, N);
    gemm128_kernel<<<gGemm, TB>>>(agg, Wg + 2 * 128 * 128, bg + 2 * 128, h1, N, 1);

    // --- classifier ---
    classifier_kernel<<<gCls, TB>>>(h1, Wc, bc, out, N);
}

// round 4
// speedup vs baseline: 1.6984x; 1.6984x over previous
#include <cuda_runtime.h>
#include <cuda_bf16.h>
#include <cstdint>

#define NNODES 100000
#define EEDGES 1600000
#define HID    128
#define NCLS   40

// ---------------- scratch (device globals; no allocation allowed) ------------
__device__ __align__(128) float g_h1[NNODES * HID];
__device__ __align__(128) float g_h2[NNODES * HID];
__device__ __align__(128) float g_agg[NNODES * HID];
__device__ __align__(128) __nv_bfloat16 g_wbhi[5 * HID * HID];   // [slot][n][k]
__device__ __align__(128) __nv_bfloat16 g_wblo[5 * HID * HID];
__device__ int   g_outdeg[NNODES];
__device__ int   g_indeg[NNODES];
__device__ int   g_cursor[NNODES];
__device__ float g_onorm[NNODES];
__device__ float g_inorm[NNODES];
__device__ int   g_rowoff[NNODES + 1];
__device__ int   g_bsums[256];
__device__ int   g_esrc[EEDGES];

// ---------------- PTX helpers -------------------------------------------------
__device__ __forceinline__ uint32_t smem_u32(const void* p) {
    uint32_t a;
    asm("{ .reg .u64 t; cvta.to.shared.u64 t, %1; cvt.u32.u64 %0, t; }" : "=r"(a) : "l"(p));
    return a;
}

#define LDSM4(r, addr)                                                          \
    asm volatile("ldmatrix.sync.aligned.m8n8.x4.shared.b16 {%0,%1,%2,%3}, [%4];" \
        : "=r"((r)[0]), "=r"((r)[1]), "=r"((r)[2]), "=r"((r)[3]) : "r"(addr))

#define MMA16816(d, a, b0, b1)                                                  \
    asm volatile("mma.sync.aligned.m16n8k16.row.col.f32.bf16.bf16.f32 "         \
        "{%0,%1,%2,%3}, {%4,%5,%6,%7}, {%8,%9}, {%0,%1,%2,%3};"                 \
        : "+f"((d)[0]), "+f"((d)[1]), "+f"((d)[2]), "+f"((d)[3])                \
        : "r"((a)[0]), "r"((a)[1]), "r"((a)[2]), "r"((a)[3]), "r"(b0), "r"(b1))

// ---------------- small prep kernels ----------------------------------------
__global__ void zero_ints_kernel(int n) {
    int i = blockIdx.x * blockDim.x + threadIdx.x;
    if (i < n) { g_outdeg[i] = 0; g_indeg[i] = 0; g_cursor[i] = 0; }
}

__global__ void degree_kernel(const int* __restrict__ src,
                              const int* __restrict__ dst, int E) {
    int e = blockIdx.x * blockDim.x + threadIdx.x;
    if (e < E) {
        atomicAdd(&g_outdeg[src[e]], 1);
        atomicAdd(&g_indeg[dst[e]], 1);
    }
}

__global__ void norm_kernel(int n) {
    int i = blockIdx.x * blockDim.x + threadIdx.x;
    if (i < n) {
        g_onorm[i] = rsqrtf((float)max(g_outdeg[i], 1));
        g_inorm[i] = rsqrtf((float)max(g_indeg[i], 1));
    }
}

__global__ void scan1_kernel(int n) {
    __shared__ int s[1024];
    int tid = threadIdx.x;
    int i = blockIdx.x * 1024 + tid;
    int v = (i < n) ? g_indeg[i] : 0;
    s[tid] = v;
    __syncthreads();
    #pragma unroll
    for (int off = 1; off < 1024; off <<= 1) {
        int t = 0;
        if (tid >= off) t = s[tid - off];
        __syncthreads();
        s[tid] += t;
        __syncthreads();
    }
    if (i < n) g_rowoff[i] = s[tid] - v;
    if (tid == 1023) g_bsums[blockIdx.x] = s[1023];
}

__global__ void scan2_kernel(int nb, int n, int E) {
    if (threadIdx.x == 0 && blockIdx.x == 0) {
        int run = 0;
        for (int b = 0; b < nb; b++) { int t = g_bsums[b]; g_bsums[b] = run; run += t; }
        g_rowoff[n] = E;
    }
}

__global__ void scan3_kernel(int n) {
    int i = blockIdx.x * 1024 + threadIdx.x;
    if (i < n) g_rowoff[i] += g_bsums[blockIdx.x];
}

__global__ void fill_kernel(const int* __restrict__ src,
                            const int* __restrict__ dst, int E) {
    int e = blockIdx.x * blockDim.x + threadIdx.x;
    if (e < E) {
        int d = dst[e];
        int pos = g_rowoff[d] + atomicAdd(&g_cursor[d], 1);
        g_esrc[pos] = src[e];
    }
}

// ---------------- weight pre-split: W[k][n] fp32 -> [n][k] bf16 hi/lo ---------
__global__ void convert_w_kernel(const float* __restrict__ W, int L,
                                 __nv_bfloat16* __restrict__ hi,
                                 __nv_bfloat16* __restrict__ lo) {
    int o = blockIdx.x * blockDim.x + threadIdx.x;
    if (o < L * HID * HID) {
        int l = o / (HID * HID);
        int r = o - l * HID * HID;
        int n = r >> 7;
        int k = r & 127;
        float v = W[l * HID * HID + k * HID + n];
        __nv_bfloat16 h = __float2bfloat16(v);
        __nv_bfloat16 lw = __float2bfloat16(v - __bfloat162float(h));
        hi[o] = h; lo[o] = lw;
    }
}

// ---------------- gather: warp per dst node, pull-mode, no atomics -----------
__global__ void __launch_bounds__(256)
gather_kernel(const float* __restrict__ h, float* __restrict__ aggout, int n) {
    int gw = (blockIdx.x * blockDim.x + threadIdx.x) >> 5;
    int lane = threadIdx.x & 31;
    if (gw >= n) return;
    int e0 = g_rowoff[gw];
    int e1 = g_rowoff[gw + 1];
    const float4* __restrict__ h4 = (const float4*)h;
    float4 acc = make_float4(0.f, 0.f, 0.f, 0.f);
    int e = e0;
    for (; e + 1 < e1; e += 2) {
        int s0 = g_esrc[e];
        int s1 = g_esrc[e + 1];
        float w0 = g_onorm[s0];
        float w1 = g_onorm[s1];
        float4 v0 = h4[s0 * 32 + lane];
        float4 v1 = h4[s1 * 32 + lane];
        acc.x = fmaf(v0.x, w0, acc.x); acc.y = fmaf(v0.y, w0, acc.y);
        acc.z = fmaf(v0.z, w0, acc.z); acc.w = fmaf(v0.w, w0, acc.w);
        acc.x = fmaf(v1.x, w1, acc.x); acc.y = fmaf(v1.y, w1, acc.y);
        acc.z = fmaf(v1.z, w1, acc.z); acc.w = fmaf(v1.w, w1, acc.w);
    }
    if (e < e1) {
        int s0 = g_esrc[e];
        float w0 = g_onorm[s0];
        float4 v0 = h4[s0 * 32 + lane];
        acc.x = fmaf(v0.x, w0, acc.x); acc.y = fmaf(v0.y, w0, acc.y);
        acc.z = fmaf(v0.z, w0, acc.z); acc.w = fmaf(v0.w, w0, acc.w);
    }
    float inn = g_inorm[gw];
    float4 r = make_float4(acc.x * inn, acc.y * inn, acc.z * inn, acc.w * inn);
    ((float4*)aggout)[gw * 32 + lane] = r;
}

// ---------------- HMMA GEMM: C[M,128] = A[M,128] @ W + b (opt relu) ----------
// Split-bf16 via mma.sync.m16n8k16 (baseline PTX, no tcgen05):
//   D = Ahi*Whi + Alo*Whi + Ahi*Wlo, fp32 accum. rel err ~1e-5.
// A fp32 in gmem, split on the fly into smem hi/lo. W pre-split bf16 [n][k].
// Smem tiles: [128 rows][128 k] bf16, row stride 256B, chunk XOR-swizzled
// (chunk ^ (row&7)) so ldmatrix.x4 is conflict-free.
#define SM_BIAS 0
#define SM_AHI  512
#define SM_ALO  (SM_AHI + 32768)
#define SM_WHI  (SM_ALO + 32768)
#define SM_WLO  (SM_WHI + 32768)
#define SM_TOTAL (SM_WLO + 32768)

__global__ void __launch_bounds__(256)
gemm_mma_kernel(const float* __restrict__ A,
                const __nv_bfloat16* __restrict__ Whi,
                const __nv_bfloat16* __restrict__ Wlo,
                const float* __restrict__ bias, float* __restrict__ C,
                int M, int relu) {
    extern __shared__ char smem[];
    uint32_t sb = smem_u32(smem);
    const int tid = threadIdx.x;
    const int lane = tid & 31;
    const int wid = tid >> 5;
    const int rowBase = blockIdx.x << 7;

    if (tid < 128) ((float*)smem)[tid] = bias[tid];

    // ---- load + split tiles: 2048 chunks of 16B per tile, 8 per thread ----
    #pragma unroll
    for (int it = 0; it < 8; it++) {
        int chunk = tid + it * 256;
        int row = chunk >> 4;
        int cc = chunk & 15;
        uint32_t so = (uint32_t)(row * 256 + ((cc ^ (row & 7)) << 4));
        int gRow = rowBase + row;
        float4 f0 = make_float4(0.f, 0.f, 0.f, 0.f), f1 = f0;
        if (gRow < M) {
            const float4* p = (const float4*)(A + (size_t)gRow * HID + cc * 8);
            f0 = p[0]; f1 = p[1];
        }
        float v[8] = {f0.x, f0.y, f0.z, f0.w, f1.x, f1.y, f1.z, f1.w};
        __nv_bfloat16 hi[8], lo[8];
        #pragma unroll
        for (int j = 0; j < 8; j++) {
            hi[j] = __float2bfloat16(v[j]);
            lo[j] = __float2bfloat16(v[j] - __bfloat162float(hi[j]));
        }
        *(uint4*)(smem + SM_AHI + so) = *(uint4*)hi;
        *(uint4*)(smem + SM_ALO + so) = *(uint4*)lo;
        *(uint4*)(smem + SM_WHI + so) = *(const uint4*)(Whi + row * HID + cc * 8);
        *(uint4*)(smem + SM_WLO + so) = *(const uint4*)(Wlo + row * HID + cc * 8);
    }
    __syncthreads();

    // ---- mainloop: warp tile 32(M) x 64(N) ----
    const int warpRow = (wid & 3) * 32;
    const int warpCol = (wid >> 2) * 64;
    float acc[2][8][4];
    #pragma unroll
    for (int mi = 0; mi < 2; mi++)
        #pragma unroll
        for (int nt = 0; nt < 8; nt++)
            #pragma unroll
            for (int q = 0; q < 4; q++) acc[mi][nt][q] = 0.f;

    const int lr = (lane & 7) + (lane & 8);   // row-in-16 per ldmatrix lane
    const int lk = (lane & 16) >> 1;          // k half (0/8)

    #pragma unroll
    for (int ks = 0; ks < 8; ks++) {
        const int k0 = ks * 16;
        uint32_t ah[2][4], al[2][4], bh[4][4], bl[4][4];
        #pragma unroll
        for (int mi = 0; mi < 2; mi++) {
            int row = warpRow + mi * 16 + lr;
            int kk = k0 + lk;
            uint32_t ad = sb + SM_AHI + row * 256 + ((((kk >> 3)) ^ (row & 7)) << 4);
            LDSM4(ah[mi], ad);
            LDSM4(al[mi], ad + (SM_ALO - SM_AHI));
        }
        #pragma unroll
        for (int nj = 0; nj < 4; nj++) {
            int row = warpCol + nj * 16 + lr;
            int kk = k0 + lk;
            uint32_t bd = sb + SM_WHI + row * 256 + ((((kk >> 3)) ^ (row & 7)) << 4);
            LDSM4(bh[nj], bd);
            LDSM4(bl[nj], bd + (SM_WLO - SM_WHI));
        }
        #pragma unroll
        for (int mi = 0; mi < 2; mi++) {
            #pragma unroll
            for (int nt = 0; nt < 8; nt++) {
                int nj = nt >> 1, up = nt & 1;
                MMA16816(acc[mi][nt], ah[mi], bh[nj][0 + up], bh[nj][2 + up]);
                MMA16816(acc[mi][nt], al[mi], bh[nj][0 + up], bh[nj][2 + up]);
                MMA16816(acc[mi][nt], ah[mi], bl[nj][0 + up], bl[nj][2 + up]);
            }
        }
    }

    // ---- epilogue ----
    const int grp = lane >> 2, qid = lane & 3;
    #pragma unroll
    for (int mi = 0; mi < 2; mi++) {
        #pragma unroll
        for (int nt = 0; nt < 8; nt++) {
            int col = warpCol + nt * 8 + qid * 2;
            float b0 = ((float*)smem)[col];
            float b1 = ((float*)smem)[col + 1];
            int r0 = rowBase + warpRow + mi * 16 + grp;
            float v0 = acc[mi][nt][0] + b0, v1 = acc[mi][nt][1] + b1;
            float v2 = acc[mi][nt][2] + b0, v3 = acc[mi][nt][3] + b1;
            if (relu) {
                v0 = fmaxf(v0, 0.f); v1 = fmaxf(v1, 0.f);
                v2 = fmaxf(v2, 0.f); v3 = fmaxf(v3, 0.f);
            }
            if (r0 < M)     *(float2*)(C + (size_t)r0 * HID + col)       = make_float2(v0, v1);
            if (r0 + 8 < M) *(float2*)(C + (size_t)(r0 + 8) * HID + col) = make_float2(v2, v3);
        }
    }
}

// ---------------- classifier: out[M,40] = A[M,128] @ Wc[128,40] + bc ---------
__global__ void __launch_bounds__(256)
classifier_kernel(const float* __restrict__ A, const float* __restrict__ Wc,
                  const float* __restrict__ bc, float* __restrict__ out, int M) {
    __shared__ float Ws[128 * 40];
    __shared__ float bs[40];
    for (int i = threadIdx.x; i < 128 * 40; i += 256) Ws[i] = Wc[i];
    if (threadIdx.x < 40) bs[threadIdx.x] = bc[threadIdx.x];
    __syncthreads();

    int lane = threadIdx.x & 31;
    int warp = (blockIdx.x * 256 + threadIdx.x) >> 5;
    int row0 = warp * 4;
    if (row0 >= M) return;

    float4 av[4];
    #pragma unroll
    for (int r = 0; r < 4; r++) {
        int row = row0 + r;
        av[r] = (row < M) ? ((const float4*)A)[row * 32 + lane]
                          : make_float4(0.f, 0.f, 0.f, 0.f);
    }

    float acc0[4] = {0.f, 0.f, 0.f, 0.f};
    float acc1[4] = {0.f, 0.f, 0.f, 0.f};
    bool hi = lane < 8;

    for (int k4 = 0; k4 < 32; k4++) {
        #pragma unroll
        for (int c = 0; c < 4; c++) {
            int k = k4 * 4 + c;
            float w0 = Ws[k * 40 + lane];
            float w1 = hi ? Ws[k * 40 + 32 + lane] : 0.f;
            #pragma unroll
            for (int r = 0; r < 4; r++) {
                float comp = (c == 0) ? av[r].x : (c == 1) ? av[r].y
                           : (c == 2) ? av[r].z : av[r].w;
                float aval = __shfl_sync(0xffffffffu, comp, k4);
                acc0[r] = fmaf(aval, w0, acc0[r]);
                acc1[r] = fmaf(aval, w1, acc1[r]);
            }
        }
    }

    #pragma unroll
    for (int r = 0; r < 4; r++) {
        int row = row0 + r;
        if (row < M) {
            out[row * 40 + lane] = acc0[r] + bs[lane];
            if (hi) out[row * 40 + 32 + lane] = acc1[r] + bs[32 + lane];
        }
    }
}

// ---------------- launch ------------------------------------------------------
extern "C" void kernel_launch(void* const* d_in, const int* in_sizes, int n_in,
                              void* d_out, int out_size) {
    const float* x   = (const float*)d_in[0];
    const int*   src = (const int*)  d_in[1];
    const int*   dst = (const int*)  d_in[2];
    const float* W1  = (const float*)d_in[3];
    const float* b1  = (const float*)d_in[4];
    const float* W2  = (const float*)d_in[5];
    const float* b2  = (const float*)d_in[6];
    const float* Wg  = (const float*)d_in[7];   // [3,128,128]
    const float* bg  = (const float*)d_in[8];   // [3,128]
    const float* Wc  = (const float*)d_in[9];
    const float* bc  = (const float*)d_in[10];
    float* out = (float*)d_out;

    const int N = in_sizes[0] / HID;
    const int E = in_sizes[1];

    float *h1, *h2, *agg;
    __nv_bfloat16 *wbhi, *wblo;
    cudaGetSymbolAddress((void**)&h1,   g_h1);
    cudaGetSymbolAddress((void**)&h2,   g_h2);
    cudaGetSymbolAddress((void**)&agg,  g_agg);
    cudaGetSymbolAddress((void**)&wbhi, g_wbhi);
    cudaGetSymbolAddress((void**)&wblo, g_wblo);

    cudaFuncSetAttribute(gemm_mma_kernel,
                         cudaFuncAttributeMaxDynamicSharedMemorySize, SM_TOTAL);

    const int TB = 256;
    const int gN = (N + TB - 1) / TB;
    const int gE = (E + TB - 1) / TB;
    const int nb = (N + 1023) / 1024;
    const int gGemm = (N + 127) / 128;
    const int gGather = (N + 7) / 8;
    const int gCls = (N + 31) / 32;

    // --- graph structure prep ---
    zero_ints_kernel<<<gN, TB>>>(N);
    degree_kernel<<<gE, TB>>>(src, dst, E);
    norm_kernel<<<gN, TB>>>(N);
    scan1_kernel<<<nb, 1024>>>(N);
    scan2_kernel<<<1, 32>>>(nb, N, E);
    scan3_kernel<<<nb, 1024>>>(N);
    fill_kernel<<<gE, TB>>>(src, dst, E);

    // --- weight pre-split (bf16 hi/lo, [n][k]) ---
    convert_w_kernel<<<(1 * HID * HID + TB - 1) / TB, TB>>>(W1, 1, wbhi + 0 * HID * HID, wblo + 0 * HID * HID);
    convert_w_kernel<<<(1 * HID * HID + TB - 1) / TB, TB>>>(W2, 1, wbhi + 1 * HID * HID, wblo + 1 * HID * HID);
    convert_w_kernel<<<(3 * HID * HID + TB - 1) / TB, TB>>>(Wg, 3, wbhi + 2 * HID * HID, wblo + 2 * HID * HID);

    // --- MLP front ---
    gemm_mma_kernel<<<gGemm, TB, SM_TOTAL>>>(x,  wbhi + 0 * HID * HID, wblo + 0 * HID * HID, b1, h1, N, 0);
    gemm_mma_kernel<<<gGemm, TB, SM_TOTAL>>>(h1, wbhi + 1 * HID * HID, wblo + 1 * HID * HID, b2, h2, N, 0);

    // --- 3 x (GraphConv + ReLU) ---
    gather_kernel<<<gGather, TB>>>(h2, agg, N);
    gemm_mma_kernel<<<gGemm, TB, SM_TOTAL>>>(agg, wbhi + 2 * HID * HID, wblo + 2 * HID * HID, bg + 0 * HID, h1, N, 1);

    gather_kernel<<<gGather, TB>>>(h1, agg, N);
    gemm_mma_kernel<<<gGemm, TB, SM_TOTAL>>>(agg, wbhi + 3 * HID * HID, wblo + 3 * HID * HID, bg + 1 * HID, h2, N, 1);

    gather_kernel<<<gGather, TB>>>(h2, agg, N);
    gemm_mma_kernel<<<gGemm, TB, SM_TOTAL>>>(agg, wbhi + 4 * HID * HID, wblo + 4 * HID * HID, bg + 2 * HID, h1, N, 1);

    // --- classifier ---
    classifier_kernel<<<gCls, TB>>>(h1, Wc, bc, out, N);
}

// round 5
// speedup vs baseline: 1.7314x; 1.0194x over previous
#include <cuda_runtime.h>
#include <cuda_bf16.h>
#include <cstdint>

#define NNODES 100000
#define EEDGES 1600000
#define HID    128
#define NCLS   40

// ---------------- scratch (device globals; no allocation allowed) ------------
__device__ __align__(128) float g_h1[NNODES * HID];
__device__ __align__(128) float g_h2[NNODES * HID];
__device__ __align__(128) float g_agg[NNODES * HID];
__device__ __align__(128) __nv_bfloat16 g_wbhi[5 * HID * HID];   // [slot][n][k]
__device__ __align__(128) __nv_bfloat16 g_wblo[5 * HID * HID];
__device__ int   g_outdeg[NNODES];
__device__ int   g_indeg[NNODES];
__device__ int   g_cursor[NNODES];
__device__ float g_onorm[NNODES];
__device__ float g_inorm[NNODES];
__device__ int   g_rowoff[NNODES + 1];
__device__ int   g_bsums[256];
__device__ int   g_esrc[EEDGES];

// ---------------- PTX helpers -------------------------------------------------
__device__ __forceinline__ uint32_t smem_u32(const void* p) {
    uint32_t a;
    asm("{ .reg .u64 t; cvta.to.shared.u64 t, %1; cvt.u32.u64 %0, t; }" : "=r"(a) : "l"(p));
    return a;
}

#define LDSM4(r, addr)                                                          \
    asm volatile("ldmatrix.sync.aligned.m8n8.x4.shared.b16 {%0,%1,%2,%3}, [%4];" \
        : "=r"((r)[0]), "=r"((r)[1]), "=r"((r)[2]), "=r"((r)[3]) : "r"(addr))

#define MMA16816(d, a, b0, b1)                                                  \
    asm volatile("mma.sync.aligned.m16n8k16.row.col.f32.bf16.bf16.f32 "         \
        "{%0,%1,%2,%3}, {%4,%5,%6,%7}, {%8,%9}, {%0,%1,%2,%3};"                 \
        : "+f"((d)[0]), "+f"((d)[1]), "+f"((d)[2]), "+f"((d)[3])                \
        : "r"((a)[0]), "r"((a)[1]), "r"((a)[2]), "r"((a)[3]), "r"(b0), "r"(b1))

#define CP_ASYNC16(smem_addr, gptr)                                             \
    asm volatile("cp.async.ca.shared.global [%0], [%1], 16;"                    \
        :: "r"(smem_addr), "l"(gptr))
#define CP_ASYNC_WAIT_ALL()                                                     \
    asm volatile("cp.async.commit_group;\n\tcp.async.wait_group 0;" ::: "memory")

// ---------------- small prep kernels ----------------------------------------
__global__ void zero_ints_kernel(int n) {
    int i = blockIdx.x * blockDim.x + threadIdx.x;
    if (i < n) { g_outdeg[i] = 0; g_indeg[i] = 0; g_cursor[i] = 0; }
}

__global__ void degree_kernel(const int* __restrict__ src,
                              const int* __restrict__ dst, int E) {
    int e = blockIdx.x * blockDim.x + threadIdx.x;
    if (e < E) {
        atomicAdd(&g_outdeg[src[e]], 1);
        atomicAdd(&g_indeg[dst[e]], 1);
    }
}

__global__ void norm_kernel(int n) {
    int i = blockIdx.x * blockDim.x + threadIdx.x;
    if (i < n) {
        g_onorm[i] = rsqrtf((float)max(g_outdeg[i], 1));
        g_inorm[i] = rsqrtf((float)max(g_indeg[i], 1));
    }
}

__global__ void scan1_kernel(int n) {
    __shared__ int s[1024];
    int tid = threadIdx.x;
    int i = blockIdx.x * 1024 + tid;
    int v = (i < n) ? g_indeg[i] : 0;
    s[tid] = v;
    __syncthreads();
    #pragma unroll
    for (int off = 1; off < 1024; off <<= 1) {
        int t = 0;
        if (tid >= off) t = s[tid - off];
        __syncthreads();
        s[tid] += t;
        __syncthreads();
    }
    if (i < n) g_rowoff[i] = s[tid] - v;
    if (tid == 1023) g_bsums[blockIdx.x] = s[1023];
}

__global__ void scan2_kernel(int nb, int n, int E) {
    if (threadIdx.x == 0 && blockIdx.x == 0) {
        int run = 0;
        for (int b = 0; b < nb; b++) { int t = g_bsums[b]; g_bsums[b] = run; run += t; }
        g_rowoff[n] = E;
    }
}

__global__ void scan3_kernel(int n) {
    int i = blockIdx.x * 1024 + threadIdx.x;
    if (i < n) g_rowoff[i] += g_bsums[blockIdx.x];
}

__global__ void fill_kernel(const int* __restrict__ src,
                            const int* __restrict__ dst, int E) {
    int e = blockIdx.x * blockDim.x + threadIdx.x;
    if (e < E) {
        int d = dst[e];
        int pos = g_rowoff[d] + atomicAdd(&g_cursor[d], 1);
        g_esrc[pos] = src[e];
    }
}

// ---------------- weight pre-split: W[k][n] fp32 -> [n][k] bf16 hi/lo ---------
__global__ void convert_w_kernel(const float* __restrict__ W, int L,
                                 __nv_bfloat16* __restrict__ hi,
                                 __nv_bfloat16* __restrict__ lo) {
    int o = blockIdx.x * blockDim.x + threadIdx.x;
    if (o < L * HID * HID) {
        int l = o / (HID * HID);
        int r = o - l * HID * HID;
        int n = r >> 7;
        int k = r & 127;
        float v = W[l * HID * HID + k * HID + n];
        __nv_bfloat16 h = __float2bfloat16(v);
        __nv_bfloat16 lw = __float2bfloat16(v - __bfloat162float(h));
        hi[o] = h; lo[o] = lw;
    }
}

// ---------------- gather: warp per dst node, pull-mode, no atomics -----------
__global__ void __launch_bounds__(256)
gather_kernel(const float* __restrict__ h, float* __restrict__ aggout, int n) {
    int gw = (blockIdx.x * blockDim.x + threadIdx.x) >> 5;
    int lane = threadIdx.x & 31;
    if (gw >= n) return;
    int e0 = g_rowoff[gw];
    int e1 = g_rowoff[gw + 1];
    const float4* __restrict__ h4 = (const float4*)h;
    float4 acc = make_float4(0.f, 0.f, 0.f, 0.f);
    int e = e0;
    for (; e + 1 < e1; e += 2) {
        int s0 = g_esrc[e];
        int s1 = g_esrc[e + 1];
        float w0 = g_onorm[s0];
        float w1 = g_onorm[s1];
        float4 v0 = h4[s0 * 32 + lane];
        float4 v1 = h4[s1 * 32 + lane];
        acc.x = fmaf(v0.x, w0, acc.x); acc.y = fmaf(v0.y, w0, acc.y);
        acc.z = fmaf(v0.z, w0, acc.z); acc.w = fmaf(v0.w, w0, acc.w);
        acc.x = fmaf(v1.x, w1, acc.x); acc.y = fmaf(v1.y, w1, acc.y);
        acc.z = fmaf(v1.z, w1, acc.z); acc.w = fmaf(v1.w, w1, acc.w);
    }
    if (e < e1) {
        int s0 = g_esrc[e];
        float w0 = g_onorm[s0];
        float4 v0 = h4[s0 * 32 + lane];
        acc.x = fmaf(v0.x, w0, acc.x); acc.y = fmaf(v0.y, w0, acc.y);
        acc.z = fmaf(v0.z, w0, acc.z); acc.w = fmaf(v0.w, w0, acc.w);
    }
    float inn = g_inorm[gw];
    float4 r = make_float4(acc.x * inn, acc.y * inn, acc.z * inn, acc.w * inn);
    ((float4*)aggout)[gw * 32 + lane] = r;
}

// ---------------- HMMA GEMM: C[M,128] = A[M,128] @ W + b (opt relu) ----------
// Split-bf16 via mma.sync.m16n8k16, D = Ahi*Whi + Alo*Whi + Ahi*Wlo (fp32 acc).
// W hi/lo resident in smem full-K (cp.async); A staged per K=32 chunk with
// register prefetch pipeline; hi|lo interleaved in one 128B row (slots 0-3 hi,
// 4-7 lo), XOR swizzle (slot ^ (row&7)) -> conflict-free ldmatrix.
// smem total ~80.5KB -> 2 CTAs/SM.
#define SM_BIAS 0
#define SM_WHI  512
#define SM_WLO  (SM_WHI + 32768)
#define SM_ACH  (SM_WLO + 32768)
#define SM_TOTAL (SM_ACH + 16384)

__global__ void __launch_bounds__(256, 2)
gemm_mma_kernel(const float* __restrict__ A,
                const __nv_bfloat16* __restrict__ Whi,
                const __nv_bfloat16* __restrict__ Wlo,
                const float* __restrict__ bias, float* __restrict__ C,
                int M, int relu) {
    extern __shared__ char smem[];
    uint32_t sb = smem_u32(smem);
    const int tid = threadIdx.x;
    const int lane = tid & 31;
    const int wid = tid >> 5;
    const int rowBase = blockIdx.x << 7;

    // ---- W tiles via cp.async (2048 x 16B chunks per tile, 8/thread/tile) ----
    #pragma unroll
    for (int it = 0; it < 8; it++) {
        int chunk = tid + it * 256;
        int row = chunk >> 4;
        int cc = chunk & 15;
        uint32_t so = (uint32_t)(row * 256 + ((cc ^ (row & 7)) << 4));
        CP_ASYNC16(sb + SM_WHI + so, (const char*)(Whi + row * HID + cc * 8));
        CP_ASYNC16(sb + SM_WLO + so, (const char*)(Wlo + row * HID + cc * 8));
    }
    if (tid < 128) ((float*)smem)[tid] = bias[tid];

    // ---- A chunk prefetch state: thread handles row=tid>>1, kh=(tid&1)*16 ----
    const int arow = tid >> 1;
    const int kh   = (tid & 1) << 4;          // 0 or 16 within 32-k chunk
    const int gRow = rowBase + arow;
    const float* aptr = A + (size_t)gRow * HID + kh;

    float4 pf[4];
    #pragma unroll
    for (int q = 0; q < 4; q++) pf[q] = make_float4(0.f, 0.f, 0.f, 0.f);
    if (gRow < M) {
        #pragma unroll
        for (int q = 0; q < 4; q++) pf[q] = *(const float4*)(aptr + 0 * 32 + q * 4);
    }

    // split + store chunk into the A buffer
    auto sts_chunk = [&]() {
        float f[16];
        #pragma unroll
        for (int q = 0; q < 4; q++) {
            f[q * 4 + 0] = pf[q].x; f[q * 4 + 1] = pf[q].y;
            f[q * 4 + 2] = pf[q].z; f[q * 4 + 3] = pf[q].w;
        }
        uint32_t hw[8], lw[8];
        #pragma unroll
        for (int j = 0; j < 8; j++) {
            __nv_bfloat16 h0 = __float2bfloat16(f[2 * j]);
            __nv_bfloat16 h1 = __float2bfloat16(f[2 * j + 1]);
            __nv_bfloat16 l0 = __float2bfloat16(f[2 * j] - __bfloat162float(h0));
            __nv_bfloat16 l1 = __float2bfloat16(f[2 * j + 1] - __bfloat162float(h1));
            __nv_bfloat162 ph = __halves2bfloat162(h0, h1);
            __nv_bfloat162 pl = __halves2bfloat162(l0, l1);
            hw[j] = *(uint32_t*)&ph;
            lw[j] = *(uint32_t*)&pl;
        }
        int s0 = kh >> 3;                      // 0 or 2
        uint32_t base = sb + SM_ACH + arow * 128;
        *(uint4*)(smem + (base - sb) + (((s0 + 0) ^ (arow & 7)) << 4)) = make_uint4(hw[0], hw[1], hw[2], hw[3]);
        *(uint4*)(smem + (base - sb) + (((s0 + 1) ^ (arow & 7)) << 4)) = make_uint4(hw[4], hw[5], hw[6], hw[7]);
        *(uint4*)(smem + (base - sb) + (((s0 + 4) ^ (arow & 7)) << 4)) = make_uint4(lw[0], lw[1], lw[2], lw[3]);
        *(uint4*)(smem + (base - sb) + (((s0 + 5) ^ (arow & 7)) << 4)) = make_uint4(lw[4], lw[5], lw[6], lw[7]);
    };
    auto ldg_chunk = [&](int c) {
        if (gRow < M) {
            #pragma unroll
            for (int q = 0; q < 4; q++) pf[q] = *(const float4*)(aptr + c * 32 + q * 4);
        } else {
            #pragma unroll
            for (int q = 0; q < 4; q++) pf[q] = make_float4(0.f, 0.f, 0.f, 0.f);
        }
    };

    sts_chunk();          // chunk 0 -> buffer
    ldg_chunk(1);         // chunk 1 -> regs
    CP_ASYNC_WAIT_ALL();  // W resident
    __syncthreads();

    // ---- mainloop: warp tile 32(M) x 64(N); 4 K-chunks x 2 k-steps ----
    const int warpRow = (wid & 3) * 32;
    const int warpCol = (wid >> 2) * 64;
    float acc[2][8][4];
    #pragma unroll
    for (int mi = 0; mi < 2; mi++)
        #pragma unroll
        for (int nt = 0; nt < 8; nt++)
            #pragma unroll
            for (int q = 0; q < 4; q++) acc[mi][nt][q] = 0.f;

    const int lr = (lane & 7) + (lane & 8);
    const int lk = (lane & 16) >> 1;          // 0 or 8

    #pragma unroll
    for (int c = 0; c < 4; c++) {
        #pragma unroll
        for (int ks = 0; ks < 2; ks++) {
            const int kic = ks * 16 + lk;     // k in chunk: 0,8,16,24
            const int sA = kic >> 3;          // hi slot 0..3
            uint32_t ah[2][4], al[2][4], bh[4][4], bl[4][4];
            #pragma unroll
            for (int mi = 0; mi < 2; mi++) {
                int row = warpRow + mi * 16 + lr;
                uint32_t ad = sb + SM_ACH + row * 128;
                LDSM4(ah[mi], ad + (((sA)     ^ (row & 7)) << 4));
                LDSM4(al[mi], ad + (((sA + 4) ^ (row & 7)) << 4));
            }
            const int kk = c * 32 + kic;
            const int kc = kk >> 3;
            #pragma unroll
            for (int nj = 0; nj < 4; nj++) {
                int row = warpCol + nj * 16 + lr;
                uint32_t bd = sb + row * 256 + ((kc ^ (row & 7)) << 4);
                LDSM4(bh[nj], bd + SM_WHI);
                LDSM4(bl[nj], bd + SM_WLO);
            }
            #pragma unroll
            for (int mi = 0; mi < 2; mi++) {
                #pragma unroll
                for (int nt = 0; nt < 8; nt++) {
                    int nj = nt >> 1, up = nt & 1;
                    MMA16816(acc[mi][nt], ah[mi], bh[nj][0 + up], bh[nj][2 + up]);
                    MMA16816(acc[mi][nt], al[mi], bh[nj][0 + up], bh[nj][2 + up]);
                    MMA16816(acc[mi][nt], ah[mi], bl[nj][0 + up], bl[nj][2 + up]);
                }
            }
        }
        if (c < 3) {
            __syncthreads();
            sts_chunk();                      // chunk c+1 regs -> buffer
            if (c < 2) ldg_chunk(c + 2);      // chunk c+2 -> regs
            __syncthreads();
        }
    }

    // ---- epilogue ----
    const int grp = lane >> 2, qid = lane & 3;
    #pragma unroll
    for (int mi = 0; mi < 2; mi++) {
        #pragma unroll
        for (int nt = 0; nt < 8; nt++) {
            int col = warpCol + nt * 8 + qid * 2;
            float b0 = ((float*)smem)[col];
            float b1 = ((float*)smem)[col + 1];
            int r0 = rowBase + warpRow + mi * 16 + grp;
            float v0 = acc[mi][nt][0] + b0, v1 = acc[mi][nt][1] + b1;
            float v2 = acc[mi][nt][2] + b0, v3 = acc[mi][nt][3] + b1;
            if (relu) {
                v0 = fmaxf(v0, 0.f); v1 = fmaxf(v1, 0.f);
                v2 = fmaxf(v2, 0.f); v3 = fmaxf(v3, 0.f);
            }
            if (r0 < M)     *(float2*)(C + (size_t)r0 * HID + col)       = make_float2(v0, v1);
            if (r0 + 8 < M) *(float2*)(C + (size_t)(r0 + 8) * HID + col) = make_float2(v2, v3);
        }
    }
}

// ---------------- classifier: out[M,40] = A[M,128] @ Wc[128,40] + bc ---------
__global__ void __launch_bounds__(256)
classifier_kernel(const float* __restrict__ A, const float* __restrict__ Wc,
                  const float* __restrict__ bc, float* __restrict__ out, int M) {
    __shared__ float Ws[128 * 40];
    __shared__ float bs[40];
    for (int i = threadIdx.x; i < 128 * 40; i += 256) Ws[i] = Wc[i];
    if (threadIdx.x < 40) bs[threadIdx.x] = bc[threadIdx.x];
    __syncthreads();

    int lane = threadIdx.x & 31;
    int warp = (blockIdx.x * 256 + threadIdx.x) >> 5;
    int row0 = warp * 4;
    if (row0 >= M) return;

    float4 av[4];
    #pragma unroll
    for (int r = 0; r < 4; r++) {
        int row = row0 + r;
        av[r] = (row < M) ? ((const float4*)A)[row * 32 + lane]
                          : make_float4(0.f, 0.f, 0.f, 0.f);
    }

    float acc0[4] = {0.f, 0.f, 0.f, 0.f};
    float acc1[4] = {0.f, 0.f, 0.f, 0.f};
    bool hi = lane < 8;

    for (int k4 = 0; k4 < 32; k4++) {
        #pragma unroll
        for (int c = 0; c < 4; c++) {
            int k = k4 * 4 + c;
            float w0 = Ws[k * 40 + lane];
            float w1 = hi ? Ws[k * 40 + 32 + lane] : 0.f;
            #pragma unroll
            for (int r = 0; r < 4; r++) {
                float comp = (c == 0) ? av[r].x : (c == 1) ? av[r].y
                           : (c == 2) ? av[r].z : av[r].w;
                float aval = __shfl_sync(0xffffffffu, comp, k4);
                acc0[r] = fmaf(aval, w0, acc0[r]);
                acc1[r] = fmaf(aval, w1, acc1[r]);
            }
        }
    }

    #pragma unroll
    for (int r = 0; r < 4; r++) {
        int row = row0 + r;
        if (row < M) {
            out[row * 40 + lane] = acc0[r] + bs[lane];
            if (hi) out[row * 40 + 32 + lane] = acc1[r] + bs[32 + lane];
        }
    }
}

// ---------------- launch ------------------------------------------------------
extern "C" void kernel_launch(void* const* d_in, const int* in_sizes, int n_in,
                              void* d_out, int out_size) {
    const float* x   = (const float*)d_in[0];
    const int*   src = (const int*)  d_in[1];
    const int*   dst = (const int*)  d_in[2];
    const float* W1  = (const float*)d_in[3];
    const float* b1  = (const float*)d_in[4];
    const float* W2  = (const float*)d_in[5];
    const float* b2  = (const float*)d_in[6];
    const float* Wg  = (const float*)d_in[7];   // [3,128,128]
    const float* bg  = (const float*)d_in[8];   // [3,128]
    const float* Wc  = (const float*)d_in[9];
    const float* bc  = (const float*)d_in[10];
    float* out = (float*)d_out;

    const int N = in_sizes[0] / HID;
    const int E = in_sizes[1];

    float *h1, *h2, *agg;
    __nv_bfloat16 *wbhi, *wblo;
    cudaGetSymbolAddress((void**)&h1,   g_h1);
    cudaGetSymbolAddress((void**)&h2,   g_h2);
    cudaGetSymbolAddress((void**)&agg,  g_agg);
    cudaGetSymbolAddress((void**)&wbhi, g_wbhi);
    cudaGetSymbolAddress((void**)&wblo, g_wblo);

    cudaFuncSetAttribute(gemm_mma_kernel,
                         cudaFuncAttributeMaxDynamicSharedMemorySize, SM_TOTAL);

    const int TB = 256;
    const int gN = (N + TB - 1) / TB;
    const int gE = (E + TB - 1) / TB;
    const int nb = (N + 1023) / 1024;
    const int gGemm = (N + 127) / 128;
    const int gGather = (N + 7) / 8;
    const int gCls = (N + 31) / 32;

    // Launch order chosen so the 6th kernel launch is a GEMM (ncu -s 5 -c 1
    // then captures GEMM instead of a scan kernel).
    convert_w_kernel<<<(1 * HID * HID + TB - 1) / TB, TB>>>(W1, 1, wbhi + 0 * HID * HID, wblo + 0 * HID * HID);   // 1
    convert_w_kernel<<<(1 * HID * HID + TB - 1) / TB, TB>>>(W2, 1, wbhi + 1 * HID * HID, wblo + 1 * HID * HID);   // 2
    convert_w_kernel<<<(3 * HID * HID + TB - 1) / TB, TB>>>(Wg, 3, wbhi + 2 * HID * HID, wblo + 2 * HID * HID);   // 3
    zero_ints_kernel<<<gN, TB>>>(N);                                                                              // 4
    degree_kernel<<<gE, TB>>>(src, dst, E);                                                                       // 5
    gemm_mma_kernel<<<gGemm, TB, SM_TOTAL>>>(x, wbhi + 0 * HID * HID, wblo + 0 * HID * HID, b1, h1, N, 0);        // 6 <- profiled
    norm_kernel<<<gN, TB>>>(N);
    scan1_kernel<<<nb, 1024>>>(N);
    scan2_kernel<<<1, 32>>>(nb, N, E);
    scan3_kernel<<<nb, 1024>>>(N);
    fill_kernel<<<gE, TB>>>(src, dst, E);

    gemm_mma_kernel<<<gGemm, TB, SM_TOTAL>>>(h1, wbhi + 1 * HID * HID, wblo + 1 * HID * HID, b2, h2, N, 0);

    gather_kernel<<<gGather, TB>>>(h2, agg, N);
    gemm_mma_kernel<<<gGemm, TB, SM_TOTAL>>>(agg, wbhi + 2 * HID * HID, wblo + 2 * HID * HID, bg + 0 * HID, h1, N, 1);

    gather_kernel<<<gGather, TB>>>(h1, agg, N);
    gemm_mma_kernel<<<gGemm, TB, SM_TOTAL>>>(agg, wbhi + 3 * HID * HID, wblo + 3 * HID * HID, bg + 1 * HID, h2, N, 1);

    gather_kernel<<<gGather, TB>>>(h2, agg, N);
    gemm_mma_kernel<<<gGemm, TB, SM_TOTAL>>>(agg, wbhi + 4 * HID * HID, wblo + 4 * HID * HID, bg + 2 * HID, h1, N, 1);

    classifier_kernel<<<gCls, TB>>>(h1, Wc, bc, out, N);
}